// round 11
// baseline (speedup 1.0000x reference)
#include <cuda_runtime.h>
#include <math.h>

#define NN 20000
#define NE 100000
#define NG 400
#define KV_BLOCKS 296

// ---------------- scratch (static device allocations only) ----------------
__device__ float g_hsA[NN*64], g_hsB[NN*64];
__device__ float g_hvA[NN*96], g_hvB[NN*96];
__device__ float g_htA[NN*80], g_htB[NN*80];
__device__ float g_geo[(size_t)NE*20];     // per CSR-slot: y1[3], y2[5], rb[10], pad2
__device__ float g_wgt[(size_t)NE*320];
__device__ int   g_src[NE];
__device__ int   g_off[NN+1];
__device__ int   g_cur[NN];
__device__ float g_k[NN*64], g_v[NN*64], g_q[NG*64];
__device__ int   g_gstart[NG+1];
__device__ float g_zr[NG*176];

__device__ __forceinline__ float siluf(float x){ return x/(1.f+expf(-x)); }

// ---------------- CSR build: zero + count (global atomics) + scan, 1 block --
__global__ void __launch_bounds__(1024) k_csr(const int* __restrict__ ei, int E, int N){
    __shared__ int warpsum[32];
    __shared__ int s_carry;
    int tid = threadIdx.x, lane = tid&31, wid = tid>>5;
    for(int i=tid;i<N;i+=1024) g_cur[i]=0;
    if(tid==0){ s_carry=0; g_off[0]=0; }
    __syncthreads();
    for(int e=tid;e<E;e+=1024) atomicAdd(&g_cur[ei[E+e]],1);
    __syncthreads();
    for(int base=0; base<N; base+=1024){
        int i = base+tid;
        int v = (i<N)? g_cur[i] : 0;
        int x = v;
        #pragma unroll
        for(int o=1;o<32;o<<=1){ int t=__shfl_up_sync(0xffffffffu,x,o); if(lane>=o) x+=t; }
        if(lane==31) warpsum[wid]=x;
        __syncthreads();
        if(wid==0){
            int w = warpsum[lane];
            #pragma unroll
            for(int o=1;o<32;o<<=1){ int t=__shfl_up_sync(0xffffffffu,w,o); if(lane>=o) w+=t; }
            warpsum[lane]=w;
        }
        __syncthreads();
        int incl = x + (wid? warpsum[wid-1]:0) + s_carry;
        if(i<N){ g_off[i+1]=incl; g_cur[i]=incl-v; }
        __syncthreads();
        if(tid==1023) s_carry = incl;
        __syncthreads();
    }
}

// ---------------- geometry + CSR scatter + feature init --------------------
__global__ void k_gs(const float* __restrict__ pos, const int* __restrict__ ei,
                     const int* __restrict__ z, const float* __restrict__ embed,
                     int N, int E){
    int idx = blockIdx.x*blockDim.x+threadIdx.x;
    if(idx < N*96) g_hvA[idx]=0.f;
    if(idx < N*80) g_htA[idx]=0.f;
    if(idx < N*64){
        int n = idx>>6, c = idx&63;
        g_hsA[idx] = embed[z[n]*64+c];
    }
    if(idx >= E) return;
    int e = idx;
    int s = ei[e], d = ei[E+e];
    float vx = pos[3*d+0]-pos[3*s+0];
    float vy = pos[3*d+1]-pos[3*s+1];
    float vz = pos[3*d+2]-pos[3*s+2];
    float elen = sqrtf(vx*vx+vy*vy+vz*vz);
    float inv = 1.f/(elen+1e-9f);
    float x=vx*inv, y=vy*inv, zz=vz*inv;
    const float s3  = 1.7320508075688772f;
    const float h5  = 1.1180339887498949f;
    const float s15 = 3.872983346207417f;
    int p = atomicAdd(&g_cur[d],1);
    g_src[p]=s;
    float* gg = g_geo + (size_t)p*20;
    float4 a0 = make_float4(s3*x, s3*y, s3*zz, s15*x*y);
    float4 a1 = make_float4(s15*y*zz, h5*(3.f*zz*zz-1.f), s15*x*zz, 0.5f*s15*(x*x-y*y));
    *(float4*)(gg)   = a0;
    *(float4*)(gg+4) = a1;
    const float sigma = 5.f/9.f;
    #pragma unroll
    for(int r=0;r<10;r++){
        float t = (elen - (float)r*(5.f/9.f))/sigma;
        gg[8+r] = expf(-0.5f*t*t);
    }
}

// ---------------- per-edge weight MLP: wgt = silu(rb@rW1+rb1)@rW2 ----------
__global__ void __launch_bounds__(160) k_wgt(const float* __restrict__ rW1,
                                             const float* __restrict__ rb1,
                                             const float* __restrict__ rW2,
                                             int l, int E){
    __shared__ float sh_hid[1024];   // 32 edges x 32 hidden
    __shared__ float sW1[320];
    __shared__ float sB1[32];
    const float* W1 = rW1 + l*320;
    const float* B1 = rb1 + l*32;
    const float* W2 = rW2 + l*10240;
    int tid = threadIdx.x;
    for(int i=tid;i<320;i+=160) sW1[i]=W1[i];
    if(tid<32) sB1[tid]=B1[tid];
    __syncthreads();
    int eb = blockIdx.x*32;
    for(int idx=tid; idx<1024; idx+=160){
        int el = idx>>5, h = idx&31;
        int e = eb+el;
        float a = sB1[h];
        if(e<E){
            const float* rb = g_geo + (size_t)e*20 + 8;
            #pragma unroll
            for(int r=0;r<10;r++) a += rb[r]*sW1[r*32+h];
        }
        sh_hid[idx] = siluf(a);
    }
    __syncthreads();
    float w0[32], w1[32];
    #pragma unroll
    for(int h=0;h<32;h++){ w0[h]=W2[h*320+tid]; w1[h]=W2[h*320+tid+160]; }
    for(int el=0; el<32; el++){
        int e = eb+el;
        if(e>=E) break;
        float a0=0.f, a1=0.f;
        #pragma unroll
        for(int h=0;h<32;h++){
            float hv = sh_hid[el*32+h];
            a0 += hv*w0[h];
            a1 += hv*w1[h];
        }
        g_wgt[(size_t)e*320+tid]     = a0;
        g_wgt[(size_t)e*320+tid+160] = a1;
    }
}

// ---------------- fused layer: gather messages (CSR) + node update ----------
__global__ void __launch_bounds__(256) k_fused(
        const float* __restrict__ Ws, const float* __restrict__ Wss,
        const float* __restrict__ Wv, const float* __restrict__ Wvv,
        const float* __restrict__ Wt, const float* __restrict__ Wtt,
        int l, int flip, int N){
    const float* hr_s = flip? g_hsB : g_hsA;
    const float* hr_v = flip? g_hvB : g_hvA;
    const float* hr_t = flip? g_htB : g_htA;
    float* hw_s = flip? g_hsA : g_hsB;
    float* hw_v = flip? g_hvA : g_hvB;
    float* hw_t = flip? g_htA : g_htB;

    __shared__ float sh_a[8*896];
    int lane = threadIdx.x & 31;
    int wloc = threadIdx.x >> 5;
    float* sa = sh_a + wloc*896;   // a0: [0,112) ; a1: 112 + c*3+d ; a2: 496 + c*5+d
    int n = blockIdx.x*8 + wloc;
    if(n>=N) return;

    float acc0[4] = {0.f,0.f,0.f,0.f};
    float acc1[4][3] = {};
    float acc2[3][5] = {};

    int beg = g_off[n], end = g_off[n+1];
    for(int ii=beg; ii<end; ii++){
        int src = g_src[ii];
        const float* Ge = g_geo + (size_t)ii*20;
        float4 Ya = *(const float4*)(Ge);
        float4 Yb = *(const float4*)(Ge+4);
        float y1x=Ya.x, y1y=Ya.y, y1z=Ya.z;
        float y20=Ya.w, y21=Yb.x, y22=Yb.y, y23=Yb.z, y24=Yb.w;
        const float* W  = g_wgt + (size_t)ii*320;
        const float* hs = hr_s + (size_t)src*64;
        float s0 = hs[lane], s1 = hs[lane+32];
        const float* hv = hr_v + (size_t)src*96 + lane*3;
        float v0 = hv[0], v1 = hv[1], v2 = hv[2];
        float t0=0.f,t1=0.f,t2=0.f,t3=0.f,t4=0.f;
        if(lane<16){
            const float* ht = hr_t + (size_t)src*80 + lane*5;
            t0=ht[0]; t1=ht[1]; t2=ht[2]; t3=ht[3]; t4=ht[4];
        }
        acc0[0] += W[lane]*s0;
        acc0[1] += W[32+lane]*s1;
        acc0[2] += W[64+lane]*(v0*y1x + v1*y1y + v2*y1z);
        acc0[3] += W[96+(lane&15)]*(t0*y20 + t1*y21 + t2*y22 + t3*y23 + t4*y24);
        float w;
        w = W[112+lane]*s0; acc1[0][0]+=w*y1x; acc1[0][1]+=w*y1y; acc1[0][2]+=w*y1z;
        w = W[144+lane]*s1; acc1[1][0]+=w*y1x; acc1[1][1]+=w*y1y; acc1[1][2]+=w*y1z;
        w = W[176+lane];    acc1[2][0]+=w*v0;  acc1[2][1]+=w*v1;  acc1[2][2]+=w*v2;
        w = W[208+lane];
        acc1[3][0]+=w*(v1*y1z - v2*y1y);
        acc1[3][1]+=w*(v2*y1x - v0*y1z);
        acc1[3][2]+=w*(v0*y1y - v1*y1x);
        w = W[240+lane]*s0; acc2[0][0]+=w*y20; acc2[0][1]+=w*y21; acc2[0][2]+=w*y22; acc2[0][3]+=w*y23; acc2[0][4]+=w*y24;
        w = W[272+lane]*s1; acc2[1][0]+=w*y20; acc2[1][1]+=w*y21; acc2[1][2]+=w*y22; acc2[1][3]+=w*y23; acc2[1][4]+=w*y24;
        w = W[304+(lane&15)]; acc2[2][0]+=w*t0; acc2[2][1]+=w*t1; acc2[2][2]+=w*t2; acc2[2][3]+=w*t3; acc2[2][4]+=w*t4;
    }

    // stage accumulated messages in shared for the warp
    sa[lane]      = acc0[0];
    sa[32+lane]   = acc0[1];
    sa[64+lane]   = acc0[2];
    if(lane<16) sa[96+lane] = acc0[3];
    #pragma unroll
    for(int k=0;k<4;k++){
        #pragma unroll
        for(int d=0;d<3;d++) sa[112 + (lane+32*k)*3 + d] = acc1[k][d];
    }
    #pragma unroll
    for(int k=0;k<2;k++){
        #pragma unroll
        for(int d=0;d<5;d++) sa[496 + (lane+32*k)*5 + d] = acc2[k][d];
    }
    if(lane<16){
        #pragma unroll
        for(int d=0;d<5;d++) sa[496 + (lane+64)*5 + d] = acc2[2][d];
    }
    __syncwarp();

    // node update: h_s = silu(a0@Ws + h_s@Wss)
    const float* Wsl  = Ws  + l*7168;
    const float* Wssl = Wss + l*4096;
    float o0=0.f, o1=0.f;
    for(int c=0;c<112;c++){
        float a = sa[c];
        o0 += a*Wsl[c*64+lane];
        o1 += a*Wsl[c*64+lane+32];
    }
    const float* hsn = hr_s + (size_t)n*64;
    for(int c=0;c<64;c++){
        float h = hsn[c];
        o0 += h*Wssl[c*64+lane];
        o1 += h*Wssl[c*64+lane+32];
    }
    hw_s[(size_t)n*64+lane]    = siluf(o0);
    hw_s[(size_t)n*64+lane+32] = siluf(o1);

    // h_v = a1@Wv + h_v@Wvv  (per dim d)
    const float* Wvl  = Wv  + l*4096;
    const float* Wvvl = Wvv + l*1024;
    float ov0=0.f, ov1=0.f, ov2=0.f;
    for(int c=0;c<128;c++){
        float wv = Wvl[c*32+lane];
        const float* av = sa + 112 + c*3;
        ov0 += av[0]*wv; ov1 += av[1]*wv; ov2 += av[2]*wv;
    }
    const float* hvn = hr_v + (size_t)n*96;
    for(int c=0;c<32;c++){
        float wv = Wvvl[c*32+lane];
        ov0 += hvn[c*3+0]*wv; ov1 += hvn[c*3+1]*wv; ov2 += hvn[c*3+2]*wv;
    }
    hw_v[(size_t)n*96+lane*3+0]=ov0;
    hw_v[(size_t)n*96+lane*3+1]=ov1;
    hw_v[(size_t)n*96+lane*3+2]=ov2;

    // h_t = a2@Wt + h_t@Wtt
    if(lane<16){
        const float* Wtl  = Wt  + l*1280;
        const float* Wttl = Wtt + l*256;
        float ot0=0.f,ot1=0.f,ot2=0.f,ot3=0.f,ot4=0.f;
        for(int c=0;c<80;c++){
            float wt = Wtl[c*16+lane];
            const float* at = sa + 496 + c*5;
            ot0+=at[0]*wt; ot1+=at[1]*wt; ot2+=at[2]*wt; ot3+=at[3]*wt; ot4+=at[4]*wt;
        }
        const float* htn = hr_t + (size_t)n*80;
        for(int c=0;c<16;c++){
            float wt = Wttl[c*16+lane];
            ot0+=htn[c*5+0]*wt; ot1+=htn[c*5+1]*wt; ot2+=htn[c*5+2]*wt;
            ot3+=htn[c*5+3]*wt; ot4+=htn[c*5+4]*wt;
        }
        hw_t[(size_t)n*80+lane*5+0]=ot0;
        hw_t[(size_t)n*80+lane*5+1]=ot1;
        hw_t[(size_t)n*80+lane*5+2]=ot2;
        hw_t[(size_t)n*80+lane*5+3]=ot3;
        hw_t[(size_t)n*80+lane*5+4]=ot4;
    }
}

// ---------------- attention head projections (shared-staged weights) -------
__global__ void __launch_bounds__(256) k_kv(const float* __restrict__ Wk, const float* __restrict__ Wvp, int N){
    __shared__ float sWk[4096], sWv[4096];
    int tid = threadIdx.x;
    for(int i=tid;i<4096;i+=256){ sWk[i]=Wk[i]; sWv[i]=Wvp[i]; }
    __syncthreads();
    int lane = tid&31, w = tid>>5;
    for(int n = blockIdx.x*8 + w; n < N; n += 8*KV_BLOCKS){
        const float* hs = g_hsA + (size_t)n*64;
        float k0=0.f,k1=0.f,v0=0.f,v1=0.f;
        for(int c=0;c<64;c++){
            float h = hs[c];
            k0 += h*sWk[c*64+lane];
            k1 += h*sWk[c*64+lane+32];
            v0 += h*sWv[c*64+lane];
            v1 += h*sWv[c*64+lane+32];
        }
        g_k[(size_t)n*64+lane]=k0; g_k[(size_t)n*64+lane+32]=k1;
        g_v[(size_t)n*64+lane]=v0; g_v[(size_t)n*64+lane+32]=v1;
    }
}
__global__ void k_q(const float* __restrict__ Wq, const int* __restrict__ absorber, int G){
    int idx = blockIdx.x*blockDim.x+threadIdx.x;
    if(idx>=G*64) return;
    int g = idx>>6, j = idx&63;
    int a = absorber[g];
    const float* hs = g_hsA + (size_t)a*64;
    float acc=0.f;
    #pragma unroll
    for(int c=0;c<64;c++) acc += hs[c]*Wq[c*64+j];
    g_q[idx]=acc;
}
__global__ void k_gstart(const int* __restrict__ batch, int N, int G){
    int g = blockIdx.x*blockDim.x+threadIdx.x;
    if(g>G) return;
    int lo=0, hi=N;
    while(lo<hi){
        int mid=(lo+hi)>>1;
        if(batch[mid]<g) lo=mid+1; else hi=mid;
    }
    g_gstart[g]=lo;
}

// ---------------- per-graph softmax attention + zr ----------------
__global__ void __launch_bounds__(128) k_attn(const int* __restrict__ absorber){
    int g = blockIdx.x;
    int tid = threadIdx.x, warp = tid>>5, lane = tid&31;
    __shared__ float qsh[64];
    __shared__ float wred[4];
    __shared__ float wc[4][64];
    int s = g_gstart[g], e = g_gstart[g+1];
    if(tid<64) qsh[tid] = g_q[g*64+tid];
    __syncthreads();
    float lmax = -1e30f;
    for(int i=s+warp; i<e; i+=4){
        float p = qsh[lane]*g_k[(size_t)i*64+lane] + qsh[lane+32]*g_k[(size_t)i*64+lane+32];
        #pragma unroll
        for(int o=16;o;o>>=1) p += __shfl_xor_sync(0xffffffffu,p,o);
        lmax = fmaxf(lmax, p*0.125f);
    }
    if(lane==0) wred[warp]=lmax;
    __syncthreads();
    float m = fmaxf(fmaxf(wred[0],wred[1]), fmaxf(wred[2],wred[3]));
    __syncthreads();
    float den=0.f, c0=0.f, c1=0.f;
    for(int i=s+warp; i<e; i+=4){
        float p = qsh[lane]*g_k[(size_t)i*64+lane] + qsh[lane+32]*g_k[(size_t)i*64+lane+32];
        #pragma unroll
        for(int o=16;o;o>>=1) p += __shfl_xor_sync(0xffffffffu,p,o);
        float ex = expf(p*0.125f - m);
        den += ex;
        c0 += ex*g_v[(size_t)i*64+lane];
        c1 += ex*g_v[(size_t)i*64+lane+32];
    }
    wc[warp][lane]=c0; wc[warp][lane+32]=c1;
    if(lane==0) wred[warp]=den;
    __syncthreads();
    int a = absorber[g];
    if(tid<64){
        float cs = wc[0][tid]+wc[1][tid]+wc[2][tid]+wc[3][tid];
        float dt = wred[0]+wred[1]+wred[2]+wred[3];
        g_zr[g*176+tid]    = g_hsA[(size_t)a*64+tid];
        g_zr[g*176+64+tid] = cs/fmaxf(dt,1e-9f);
    }
    if(tid>=64 && tid<96){
        int c = tid-64;
        const float* hv = g_hvA + (size_t)a*96 + c*3;
        g_zr[g*176+128+c] = hv[0]*hv[0]+hv[1]*hv[1]+hv[2]*hv[2];
    }
    if(tid>=96 && tid<112){
        int c = tid-96;
        const float* ht = g_htA + (size_t)a*80 + c*5;
        float sacc=0.f;
        #pragma unroll
        for(int d=0;d<5;d++) sacc += ht[d]*ht[d];
        g_zr[g*176+160+c]=sacc;
    }
}

// ---------------- readout MLP ----------------
__global__ void __launch_bounds__(128) k_out(const float* __restrict__ Wr1, const float* __restrict__ br1,
                                             const float* __restrict__ Wr2, const float* __restrict__ br2,
                                             float* __restrict__ out){
    int g = blockIdx.x, tid = threadIdx.x;
    __shared__ float zsh[176];
    __shared__ float hsh[128];
    for(int i=tid;i<176;i+=128) zsh[i]=g_zr[g*176+i];
    __syncthreads();
    float acc = br1[tid];
    for(int i=0;i<176;i++) acc += zsh[i]*Wr1[i*128+tid];
    hsh[tid]=siluf(acc);
    __syncthreads();
    float o = br2[tid];
    #pragma unroll
    for(int i=0;i<128;i++) o += hsh[i]*Wr2[i*128+tid];
    out[g*128+tid]=o;
}

// ---------------- launch ----------------
extern "C" void kernel_launch(void* const* d_in, const int* in_sizes, int n_in,
                              void* d_out, int out_size){
    const int*   z        = (const int*)  d_in[0];
    const float* pos      = (const float*)d_in[1];
    const int*   ei       = (const int*)  d_in[2];
    const int*   batch    = (const int*)  d_in[3];
    const int*   absorber = (const int*)  d_in[4];
    const float* embed    = (const float*)d_in[5];
    const float* rW1      = (const float*)d_in[6];
    const float* rb1      = (const float*)d_in[7];
    const float* rW2      = (const float*)d_in[8];
    const float* Ws       = (const float*)d_in[9];
    const float* Wss      = (const float*)d_in[10];
    const float* Wv       = (const float*)d_in[11];
    const float* Wvv      = (const float*)d_in[12];
    const float* Wt       = (const float*)d_in[13];
    const float* Wtt      = (const float*)d_in[14];
    const float* Wq       = (const float*)d_in[15];
    const float* Wk       = (const float*)d_in[16];
    const float* Wvp      = (const float*)d_in[17];
    const float* Wr1      = (const float*)d_in[18];
    const float* br1      = (const float*)d_in[19];
    const float* Wr2      = (const float*)d_in[20];
    const float* br2      = (const float*)d_in[21];
    float* out = (float*)d_out;

    int N = in_sizes[0];
    int E = in_sizes[2]/2;
    int G = in_sizes[4];
    if(N>NN || E>NE || G>NG) return;

    int gs_work = N*96 > E ? N*96 : E;

    k_csr <<<1, 1024>>>(ei, E, N);                               // launch 1
    k_gs  <<<(gs_work+255)/256, 256>>>(pos, ei, z, embed, N, E); // launch 2

    for(int l=0;l<4;l++){
        k_wgt  <<<(E+31)/32, 160>>>(rW1, rb1, rW2, l, E);        // launch 3 (l=0)
        k_fused<<<(N+7)/8, 256>>>(Ws, Wss, Wv, Wvv, Wt, Wtt, l, l&1, N); // launch 4 (l=0) <- profiled
    }

    k_kv    <<<KV_BLOCKS, 256>>>(Wk, Wvp, N);
    k_q     <<<(G*64+255)/256, 256>>>(Wq, absorber, G);
    k_gstart<<<(G+1+127)/128, 128>>>(batch, N, G);
    k_attn  <<<G, 128>>>(absorber);
    k_out   <<<G, 128>>>(Wr1, br1, Wr2, br2, out);
}

// round 12
// speedup vs baseline: 1.0746x; 1.0746x over previous
#include <cuda_runtime.h>
#include <math.h>

#define NN 20000
#define NE 100000
#define NG 400
#define KV_BLOCKS 296

// ---------------- scratch (static device allocations only) ----------------
__device__ float g_hsA[NN*64], g_hsB[NN*64];
__device__ float g_hvA[NN*96], g_hvB[NN*96];
__device__ float g_htA[NN*80], g_htB[NN*80];
__device__ float g_geo[(size_t)NE*20];     // per CSR-slot: y1[3], y2[5], rb[10], pad2
__device__ float g_wgt[(size_t)NE*320];
__device__ int   g_src[NE];
__device__ int   g_off[NN+1];
__device__ int   g_cur[NN];
__device__ float g_k[NN*64], g_v[NN*64], g_q[NG*64];
__device__ int   g_gstart[NG+1];
__device__ float g_zr[NG*176];

__device__ __forceinline__ float siluf(float x){ return x/(1.f+expf(-x)); }

// ---------------- CSR build: zero + count (global atomics) + scan, 1 block --
__global__ void __launch_bounds__(1024) k_csr(const int* __restrict__ ei, int E, int N){
    __shared__ int warpsum[32];
    __shared__ int s_carry;
    int tid = threadIdx.x, lane = tid&31, wid = tid>>5;
    for(int i=tid;i<N;i+=1024) g_cur[i]=0;
    if(tid==0){ s_carry=0; g_off[0]=0; }
    __syncthreads();
    for(int e=tid;e<E;e+=1024) atomicAdd(&g_cur[ei[E+e]],1);
    __syncthreads();
    for(int base=0; base<N; base+=1024){
        int i = base+tid;
        int v = (i<N)? g_cur[i] : 0;
        int x = v;
        #pragma unroll
        for(int o=1;o<32;o<<=1){ int t=__shfl_up_sync(0xffffffffu,x,o); if(lane>=o) x+=t; }
        if(lane==31) warpsum[wid]=x;
        __syncthreads();
        if(wid==0){
            int w = warpsum[lane];
            #pragma unroll
            for(int o=1;o<32;o<<=1){ int t=__shfl_up_sync(0xffffffffu,w,o); if(lane>=o) w+=t; }
            warpsum[lane]=w;
        }
        __syncthreads();
        int incl = x + (wid? warpsum[wid-1]:0) + s_carry;
        if(i<N){ g_off[i+1]=incl; g_cur[i]=incl-v; }
        __syncthreads();
        if(tid==1023) s_carry = incl;
        __syncthreads();
    }
}

// ---------------- geometry + CSR scatter + feature init --------------------
__global__ void k_gs(const float* __restrict__ pos, const int* __restrict__ ei,
                     const int* __restrict__ z, const float* __restrict__ embed,
                     int N, int E){
    int idx = blockIdx.x*blockDim.x+threadIdx.x;
    if(idx < N*96) g_hvA[idx]=0.f;
    if(idx < N*80) g_htA[idx]=0.f;
    if(idx < N*64){
        int n = idx>>6, c = idx&63;
        g_hsA[idx] = embed[z[n]*64+c];
    }
    if(idx >= E) return;
    int e = idx;
    int s = ei[e], d = ei[E+e];
    float vx = pos[3*d+0]-pos[3*s+0];
    float vy = pos[3*d+1]-pos[3*s+1];
    float vz = pos[3*d+2]-pos[3*s+2];
    float elen = sqrtf(vx*vx+vy*vy+vz*vz);
    float inv = 1.f/(elen+1e-9f);
    float x=vx*inv, y=vy*inv, zz=vz*inv;
    const float s3  = 1.7320508075688772f;
    const float h5  = 1.1180339887498949f;
    const float s15 = 3.872983346207417f;
    int p = atomicAdd(&g_cur[d],1);
    g_src[p]=s;
    float* gg = g_geo + (size_t)p*20;
    float4 a0 = make_float4(s3*x, s3*y, s3*zz, s15*x*y);
    float4 a1 = make_float4(s15*y*zz, h5*(3.f*zz*zz-1.f), s15*x*zz, 0.5f*s15*(x*x-y*y));
    *(float4*)(gg)   = a0;
    *(float4*)(gg+4) = a1;
    const float sigma = 5.f/9.f;
    #pragma unroll
    for(int r=0;r<10;r++){
        float t = (elen - (float)r*(5.f/9.f))/sigma;
        gg[8+r] = expf(-0.5f*t*t);
    }
}

// ---------------- group start offsets (binary search on sorted batch) ------
__global__ void k_gstart(const int* __restrict__ batch, int N, int G){
    int g = blockIdx.x*blockDim.x+threadIdx.x;
    if(g>G) return;
    int lo=0, hi=N;
    while(lo<hi){
        int mid=(lo+hi)>>1;
        if(batch[mid]<g) lo=mid+1; else hi=mid;
    }
    g_gstart[g]=lo;
}

// ---------------- per-edge weight MLP: wgt = silu(rb@rW1+rb1)@rW2 ----------
__global__ void __launch_bounds__(160) k_wgt(const float* __restrict__ rW1,
                                             const float* __restrict__ rb1,
                                             const float* __restrict__ rW2,
                                             int l, int E){
    __shared__ float sh_hid[1024];   // 32 edges x 32 hidden
    __shared__ float sW1[320];
    __shared__ float sB1[32];
    const float* W1 = rW1 + l*320;
    const float* B1 = rb1 + l*32;
    const float* W2 = rW2 + l*10240;
    int tid = threadIdx.x;
    for(int i=tid;i<320;i+=160) sW1[i]=W1[i];
    if(tid<32) sB1[tid]=B1[tid];
    __syncthreads();
    int eb = blockIdx.x*32;
    for(int idx=tid; idx<1024; idx+=160){
        int el = idx>>5, h = idx&31;
        int e = eb+el;
        float a = sB1[h];
        if(e<E){
            const float* rb = g_geo + (size_t)e*20 + 8;
            #pragma unroll
            for(int r=0;r<10;r++) a += rb[r]*sW1[r*32+h];
        }
        sh_hid[idx] = siluf(a);
    }
    __syncthreads();
    float w0[32], w1[32];
    #pragma unroll
    for(int h=0;h<32;h++){ w0[h]=W2[h*320+tid]; w1[h]=W2[h*320+tid+160]; }
    for(int el=0; el<32; el++){
        int e = eb+el;
        if(e>=E) break;
        float a0=0.f, a1=0.f;
        #pragma unroll
        for(int h=0;h<32;h++){
            float hv = sh_hid[el*32+h];
            a0 += hv*w0[h];
            a1 += hv*w1[h];
        }
        g_wgt[(size_t)e*320+tid]     = a0;
        g_wgt[(size_t)e*320+tid+160] = a1;
    }
}

// ---------------- fused layer: gather messages (CSR) + node update ----------
// __launch_bounds__(256,4): cap regs at 64 so 4 blocks/SM fit (32 warps vs 24
// at the previous 79 regs) — kernel is L1-latency-exposed at occ 28.5%.
__global__ void __launch_bounds__(256, 4) k_fused(
        const float* __restrict__ Ws, const float* __restrict__ Wss,
        const float* __restrict__ Wv, const float* __restrict__ Wvv,
        const float* __restrict__ Wt, const float* __restrict__ Wtt,
        int l, int flip, int N){
    const float* hr_s = flip? g_hsB : g_hsA;
    const float* hr_v = flip? g_hvB : g_hvA;
    const float* hr_t = flip? g_htB : g_htA;
    float* hw_s = flip? g_hsA : g_hsB;
    float* hw_v = flip? g_hvA : g_hvB;
    float* hw_t = flip? g_htA : g_htB;

    __shared__ float sh_a[8*896];
    int lane = threadIdx.x & 31;
    int wloc = threadIdx.x >> 5;
    float* sa = sh_a + wloc*896;   // a0: [0,112) ; a1: 112 + c*3+d ; a2: 496 + c*5+d
    int n = blockIdx.x*8 + wloc;
    if(n>=N) return;

    float acc0[4] = {0.f,0.f,0.f,0.f};
    float acc1[4][3] = {};
    float acc2[3][5] = {};

    int beg = g_off[n], end = g_off[n+1];
    for(int ii=beg; ii<end; ii++){
        int src = g_src[ii];
        const float* Ge = g_geo + (size_t)ii*20;
        float4 Ya = *(const float4*)(Ge);
        float4 Yb = *(const float4*)(Ge+4);
        float y1x=Ya.x, y1y=Ya.y, y1z=Ya.z;
        float y20=Ya.w, y21=Yb.x, y22=Yb.y, y23=Yb.z, y24=Yb.w;
        const float* W  = g_wgt + (size_t)ii*320;
        const float* hs = hr_s + (size_t)src*64;
        float s0 = hs[lane], s1 = hs[lane+32];
        const float* hv = hr_v + (size_t)src*96 + lane*3;
        float v0 = hv[0], v1 = hv[1], v2 = hv[2];
        float t0=0.f,t1=0.f,t2=0.f,t3=0.f,t4=0.f;
        if(lane<16){
            const float* ht = hr_t + (size_t)src*80 + lane*5;
            t0=ht[0]; t1=ht[1]; t2=ht[2]; t3=ht[3]; t4=ht[4];
        }
        acc0[0] += W[lane]*s0;
        acc0[1] += W[32+lane]*s1;
        acc0[2] += W[64+lane]*(v0*y1x + v1*y1y + v2*y1z);
        acc0[3] += W[96+(lane&15)]*(t0*y20 + t1*y21 + t2*y22 + t3*y23 + t4*y24);
        float w;
        w = W[112+lane]*s0; acc1[0][0]+=w*y1x; acc1[0][1]+=w*y1y; acc1[0][2]+=w*y1z;
        w = W[144+lane]*s1; acc1[1][0]+=w*y1x; acc1[1][1]+=w*y1y; acc1[1][2]+=w*y1z;
        w = W[176+lane];    acc1[2][0]+=w*v0;  acc1[2][1]+=w*v1;  acc1[2][2]+=w*v2;
        w = W[208+lane];
        acc1[3][0]+=w*(v1*y1z - v2*y1y);
        acc1[3][1]+=w*(v2*y1x - v0*y1z);
        acc1[3][2]+=w*(v0*y1y - v1*y1x);
        w = W[240+lane]*s0; acc2[0][0]+=w*y20; acc2[0][1]+=w*y21; acc2[0][2]+=w*y22; acc2[0][3]+=w*y23; acc2[0][4]+=w*y24;
        w = W[272+lane]*s1; acc2[1][0]+=w*y20; acc2[1][1]+=w*y21; acc2[1][2]+=w*y22; acc2[1][3]+=w*y23; acc2[1][4]+=w*y24;
        w = W[304+(lane&15)]; acc2[2][0]+=w*t0; acc2[2][1]+=w*t1; acc2[2][2]+=w*t2; acc2[2][3]+=w*t3; acc2[2][4]+=w*t4;
    }

    // stage accumulated messages in shared for the warp
    sa[lane]      = acc0[0];
    sa[32+lane]   = acc0[1];
    sa[64+lane]   = acc0[2];
    if(lane<16) sa[96+lane] = acc0[3];
    #pragma unroll
    for(int k=0;k<4;k++){
        #pragma unroll
        for(int d=0;d<3;d++) sa[112 + (lane+32*k)*3 + d] = acc1[k][d];
    }
    #pragma unroll
    for(int k=0;k<2;k++){
        #pragma unroll
        for(int d=0;d<5;d++) sa[496 + (lane+32*k)*5 + d] = acc2[k][d];
    }
    if(lane<16){
        #pragma unroll
        for(int d=0;d<5;d++) sa[496 + (lane+64)*5 + d] = acc2[2][d];
    }
    __syncwarp();

    // node update: h_s = silu(a0@Ws + h_s@Wss)
    const float* Wsl  = Ws  + l*7168;
    const float* Wssl = Wss + l*4096;
    float o0=0.f, o1=0.f;
    for(int c=0;c<112;c++){
        float a = sa[c];
        o0 += a*Wsl[c*64+lane];
        o1 += a*Wsl[c*64+lane+32];
    }
    const float* hsn = hr_s + (size_t)n*64;
    for(int c=0;c<64;c++){
        float h = hsn[c];
        o0 += h*Wssl[c*64+lane];
        o1 += h*Wssl[c*64+lane+32];
    }
    hw_s[(size_t)n*64+lane]    = siluf(o0);
    hw_s[(size_t)n*64+lane+32] = siluf(o1);

    // h_v = a1@Wv + h_v@Wvv  (per dim d)
    const float* Wvl  = Wv  + l*4096;
    const float* Wvvl = Wvv + l*1024;
    float ov0=0.f, ov1=0.f, ov2=0.f;
    for(int c=0;c<128;c++){
        float wv = Wvl[c*32+lane];
        const float* av = sa + 112 + c*3;
        ov0 += av[0]*wv; ov1 += av[1]*wv; ov2 += av[2]*wv;
    }
    const float* hvn = hr_v + (size_t)n*96;
    for(int c=0;c<32;c++){
        float wv = Wvvl[c*32+lane];
        ov0 += hvn[c*3+0]*wv; ov1 += hvn[c*3+1]*wv; ov2 += hvn[c*3+2]*wv;
    }
    hw_v[(size_t)n*96+lane*3+0]=ov0;
    hw_v[(size_t)n*96+lane*3+1]=ov1;
    hw_v[(size_t)n*96+lane*3+2]=ov2;

    // h_t = a2@Wt + h_t@Wtt
    if(lane<16){
        const float* Wtl  = Wt  + l*1280;
        const float* Wttl = Wtt + l*256;
        float ot0=0.f,ot1=0.f,ot2=0.f,ot3=0.f,ot4=0.f;
        for(int c=0;c<80;c++){
            float wt = Wtl[c*16+lane];
            const float* at = sa + 496 + c*5;
            ot0+=at[0]*wt; ot1+=at[1]*wt; ot2+=at[2]*wt; ot3+=at[3]*wt; ot4+=at[4]*wt;
        }
        const float* htn = hr_t + (size_t)n*80;
        for(int c=0;c<16;c++){
            float wt = Wttl[c*16+lane];
            ot0+=htn[c*5+0]*wt; ot1+=htn[c*5+1]*wt; ot2+=htn[c*5+2]*wt;
            ot3+=htn[c*5+3]*wt; ot4+=htn[c*5+4]*wt;
        }
        hw_t[(size_t)n*80+lane*5+0]=ot0;
        hw_t[(size_t)n*80+lane*5+1]=ot1;
        hw_t[(size_t)n*80+lane*5+2]=ot2;
        hw_t[(size_t)n*80+lane*5+3]=ot3;
        hw_t[(size_t)n*80+lane*5+4]=ot4;
    }
}

// ---------------- attention head projections (shared-staged weights) -------
__global__ void __launch_bounds__(256) k_kv(const float* __restrict__ Wk, const float* __restrict__ Wvp, int N){
    __shared__ float sWk[4096], sWv[4096];
    int tid = threadIdx.x;
    for(int i=tid;i<4096;i+=256){ sWk[i]=Wk[i]; sWv[i]=Wvp[i]; }
    __syncthreads();
    int lane = tid&31, w = tid>>5;
    for(int n = blockIdx.x*8 + w; n < N; n += 8*KV_BLOCKS){
        const float* hs = g_hsA + (size_t)n*64;
        float k0=0.f,k1=0.f,v0=0.f,v1=0.f;
        for(int c=0;c<64;c++){
            float h = hs[c];
            k0 += h*sWk[c*64+lane];
            k1 += h*sWk[c*64+lane+32];
            v0 += h*sWv[c*64+lane];
            v1 += h*sWv[c*64+lane+32];
        }
        g_k[(size_t)n*64+lane]=k0; g_k[(size_t)n*64+lane+32]=k1;
        g_v[(size_t)n*64+lane]=v0; g_v[(size_t)n*64+lane+32]=v1;
    }
}
__global__ void k_q(const float* __restrict__ Wq, const int* __restrict__ absorber, int G){
    int idx = blockIdx.x*blockDim.x+threadIdx.x;
    if(idx>=G*64) return;
    int g = idx>>6, j = idx&63;
    int a = absorber[g];
    const float* hs = g_hsA + (size_t)a*64;
    float acc=0.f;
    #pragma unroll
    for(int c=0;c<64;c++) acc += hs[c]*Wq[c*64+j];
    g_q[idx]=acc;
}

// ---------------- per-graph softmax attention + zr ----------------
__global__ void __launch_bounds__(128) k_attn(const int* __restrict__ absorber){
    int g = blockIdx.x;
    int tid = threadIdx.x, warp = tid>>5, lane = tid&31;
    __shared__ float qsh[64];
    __shared__ float wred[4];
    __shared__ float wc[4][64];
    int s = g_gstart[g], e = g_gstart[g+1];
    if(tid<64) qsh[tid] = g_q[g*64+tid];
    __syncthreads();
    float lmax = -1e30f;
    for(int i=s+warp; i<e; i+=4){
        float p = qsh[lane]*g_k[(size_t)i*64+lane] + qsh[lane+32]*g_k[(size_t)i*64+lane+32];
        #pragma unroll
        for(int o=16;o;o>>=1) p += __shfl_xor_sync(0xffffffffu,p,o);
        lmax = fmaxf(lmax, p*0.125f);
    }
    if(lane==0) wred[warp]=lmax;
    __syncthreads();
    float m = fmaxf(fmaxf(wred[0],wred[1]), fmaxf(wred[2],wred[3]));
    __syncthreads();
    float den=0.f, c0=0.f, c1=0.f;
    for(int i=s+warp; i<e; i+=4){
        float p = qsh[lane]*g_k[(size_t)i*64+lane] + qsh[lane+32]*g_k[(size_t)i*64+lane+32];
        #pragma unroll
        for(int o=16;o;o>>=1) p += __shfl_xor_sync(0xffffffffu,p,o);
        float ex = expf(p*0.125f - m);
        den += ex;
        c0 += ex*g_v[(size_t)i*64+lane];
        c1 += ex*g_v[(size_t)i*64+lane+32];
    }
    wc[warp][lane]=c0; wc[warp][lane+32]=c1;
    if(lane==0) wred[warp]=den;
    __syncthreads();
    int a = absorber[g];
    if(tid<64){
        float cs = wc[0][tid]+wc[1][tid]+wc[2][tid]+wc[3][tid];
        float dt = wred[0]+wred[1]+wred[2]+wred[3];
        g_zr[g*176+tid]    = g_hsA[(size_t)a*64+tid];
        g_zr[g*176+64+tid] = cs/fmaxf(dt,1e-9f);
    }
    if(tid>=64 && tid<96){
        int c = tid-64;
        const float* hv = g_hvA + (size_t)a*96 + c*3;
        g_zr[g*176+128+c] = hv[0]*hv[0]+hv[1]*hv[1]+hv[2]*hv[2];
    }
    if(tid>=96 && tid<112){
        int c = tid-96;
        const float* ht = g_htA + (size_t)a*80 + c*5;
        float sacc=0.f;
        #pragma unroll
        for(int d=0;d<5;d++) sacc += ht[d]*ht[d];
        g_zr[g*176+160+c]=sacc;
    }
}

// ---------------- readout MLP ----------------
__global__ void __launch_bounds__(128) k_out(const float* __restrict__ Wr1, const float* __restrict__ br1,
                                             const float* __restrict__ Wr2, const float* __restrict__ br2,
                                             float* __restrict__ out){
    int g = blockIdx.x, tid = threadIdx.x;
    __shared__ float zsh[176];
    __shared__ float hsh[128];
    for(int i=tid;i<176;i+=128) zsh[i]=g_zr[g*176+i];
    __syncthreads();
    float acc = br1[tid];
    for(int i=0;i<176;i++) acc += zsh[i]*Wr1[i*128+tid];
    hsh[tid]=siluf(acc);
    __syncthreads();
    float o = br2[tid];
    #pragma unroll
    for(int i=0;i<128;i++) o += hsh[i]*Wr2[i*128+tid];
    out[g*128+tid]=o;
}

// ---------------- launch ----------------
extern "C" void kernel_launch(void* const* d_in, const int* in_sizes, int n_in,
                              void* d_out, int out_size){
    const int*   z        = (const int*)  d_in[0];
    const float* pos      = (const float*)d_in[1];
    const int*   ei       = (const int*)  d_in[2];
    const int*   batch    = (const int*)  d_in[3];
    const int*   absorber = (const int*)  d_in[4];
    const float* embed    = (const float*)d_in[5];
    const float* rW1      = (const float*)d_in[6];
    const float* rb1      = (const float*)d_in[7];
    const float* rW2      = (const float*)d_in[8];
    const float* Ws       = (const float*)d_in[9];
    const float* Wss      = (const float*)d_in[10];
    const float* Wv       = (const float*)d_in[11];
    const float* Wvv      = (const float*)d_in[12];
    const float* Wt       = (const float*)d_in[13];
    const float* Wtt      = (const float*)d_in[14];
    const float* Wq       = (const float*)d_in[15];
    const float* Wk       = (const float*)d_in[16];
    const float* Wvp      = (const float*)d_in[17];
    const float* Wr1      = (const float*)d_in[18];
    const float* br1      = (const float*)d_in[19];
    const float* Wr2      = (const float*)d_in[20];
    const float* br2      = (const float*)d_in[21];
    float* out = (float*)d_out;

    int N = in_sizes[0];
    int E = in_sizes[2]/2;
    int G = in_sizes[4];
    if(N>NN || E>NE || G>NG) return;

    int gs_work = N*96 > E ? N*96 : E;

    k_csr   <<<1, 1024>>>(ei, E, N);                               // launch 1
    k_gs    <<<(gs_work+255)/256, 256>>>(pos, ei, z, embed, N, E); // launch 2
    k_gstart<<<(G+1+127)/128, 128>>>(batch, N, G);                 // launch 3 (indep of layers)

    for(int l=0;l<4;l++){
        k_wgt  <<<(E+31)/32, 160>>>(rW1, rb1, rW2, l, E);          // launch 4 (l=0) <- profiled
        k_fused<<<(N+7)/8, 256>>>(Ws, Wss, Wv, Wvv, Wt, Wtt, l, l&1, N);
    }

    k_kv    <<<KV_BLOCKS, 256>>>(Wk, Wvp, N);
    k_q     <<<(G*64+255)/256, 256>>>(Wq, absorber, G);
    k_attn  <<<G, 128>>>(absorber);
    k_out   <<<G, 128>>>(Wr1, br1, Wr2, br2, out);
}

// round 13
// speedup vs baseline: 1.0959x; 1.0198x over previous
#include <cuda_runtime.h>
#include <cuda_fp16.h>
#include <math.h>

#define NN 20000
#define NE 100000
#define NG 400
#define KV_BLOCKS 296

// ---------------- scratch (static device allocations only) ----------------
__device__ float g_hsA[NN*64], g_hsB[NN*64];
__device__ float g_hvA[NN*96], g_hvB[NN*96];
__device__ float g_htA[NN*80], g_htB[NN*80];
__device__ float g_geo[(size_t)NE*20];     // per CSR-slot: y1[3], y2[5], rb[10], pad2
__device__ __half g_wgt[(size_t)NE*320];   // fp16: halves DRAM round-trip wgt->fused
__device__ int   g_src[NE];
__device__ int   g_off[NN+1];
__device__ int   g_cur[NN];
__device__ float g_k[NN*64], g_v[NN*64], g_q[NG*64];
__device__ int   g_gstart[NG+1];
__device__ float g_zr[NG*176];

__device__ __forceinline__ float siluf(float x){ return x/(1.f+expf(-x)); }

// ---------------- CSR build: zero + count (global atomics) + scan, 1 block --
__global__ void __launch_bounds__(1024) k_csr(const int* __restrict__ ei, int E, int N){
    __shared__ int warpsum[32];
    __shared__ int s_carry;
    int tid = threadIdx.x, lane = tid&31, wid = tid>>5;
    for(int i=tid;i<N;i+=1024) g_cur[i]=0;
    if(tid==0){ s_carry=0; g_off[0]=0; }
    __syncthreads();
    for(int e=tid;e<E;e+=1024) atomicAdd(&g_cur[ei[E+e]],1);
    __syncthreads();
    for(int base=0; base<N; base+=1024){
        int i = base+tid;
        int v = (i<N)? g_cur[i] : 0;
        int x = v;
        #pragma unroll
        for(int o=1;o<32;o<<=1){ int t=__shfl_up_sync(0xffffffffu,x,o); if(lane>=o) x+=t; }
        if(lane==31) warpsum[wid]=x;
        __syncthreads();
        if(wid==0){
            int w = warpsum[lane];
            #pragma unroll
            for(int o=1;o<32;o<<=1){ int t=__shfl_up_sync(0xffffffffu,w,o); if(lane>=o) w+=t; }
            warpsum[lane]=w;
        }
        __syncthreads();
        int incl = x + (wid? warpsum[wid-1]:0) + s_carry;
        if(i<N){ g_off[i+1]=incl; g_cur[i]=incl-v; }
        __syncthreads();
        if(tid==1023) s_carry = incl;
        __syncthreads();
    }
}

// ---------------- geometry + CSR scatter + feature init --------------------
__global__ void k_gs(const float* __restrict__ pos, const int* __restrict__ ei,
                     const int* __restrict__ z, const float* __restrict__ embed,
                     int N, int E){
    int idx = blockIdx.x*blockDim.x+threadIdx.x;
    if(idx < N*96) g_hvA[idx]=0.f;
    if(idx < N*80) g_htA[idx]=0.f;
    if(idx < N*64){
        int n = idx>>6, c = idx&63;
        g_hsA[idx] = embed[z[n]*64+c];
    }
    if(idx >= E) return;
    int e = idx;
    int s = ei[e], d = ei[E+e];
    float vx = pos[3*d+0]-pos[3*s+0];
    float vy = pos[3*d+1]-pos[3*s+1];
    float vz = pos[3*d+2]-pos[3*s+2];
    float elen = sqrtf(vx*vx+vy*vy+vz*vz);
    float inv = 1.f/(elen+1e-9f);
    float x=vx*inv, y=vy*inv, zz=vz*inv;
    const float s3  = 1.7320508075688772f;
    const float h5  = 1.1180339887498949f;
    const float s15 = 3.872983346207417f;
    int p = atomicAdd(&g_cur[d],1);
    g_src[p]=s;
    float* gg = g_geo + (size_t)p*20;
    float4 a0 = make_float4(s3*x, s3*y, s3*zz, s15*x*y);
    float4 a1 = make_float4(s15*y*zz, h5*(3.f*zz*zz-1.f), s15*x*zz, 0.5f*s15*(x*x-y*y));
    *(float4*)(gg)   = a0;
    *(float4*)(gg+4) = a1;
    const float sigma = 5.f/9.f;
    #pragma unroll
    for(int r=0;r<10;r++){
        float t = (elen - (float)r*(5.f/9.f))/sigma;
        gg[8+r] = expf(-0.5f*t*t);
    }
}

// ---------------- group start offsets (binary search on sorted batch) ------
__global__ void k_gstart(const int* __restrict__ batch, int N, int G){
    int g = blockIdx.x*blockDim.x+threadIdx.x;
    if(g>G) return;
    int lo=0, hi=N;
    while(lo<hi){
        int mid=(lo+hi)>>1;
        if(batch[mid]<g) lo=mid+1; else hi=mid;
    }
    g_gstart[g]=lo;
}

// ---------------- per-edge weight MLP: wgt = silu(rb@rW1+rb1)@rW2 ----------
// 320 threads: one output column per thread, 32 W2 coeffs in registers.
__global__ void __launch_bounds__(320) k_wgt(const float* __restrict__ rW1,
                                             const float* __restrict__ rb1,
                                             const float* __restrict__ rW2,
                                             int l, int E){
    __shared__ float sh_hid[1024];   // 32 edges x 32 hidden
    __shared__ float sW1[320];
    __shared__ float sB1[32];
    const float* W1 = rW1 + l*320;
    const float* B1 = rb1 + l*32;
    const float* W2 = rW2 + l*10240;
    int tid = threadIdx.x;
    sW1[tid]=W1[tid];
    if(tid<32) sB1[tid]=B1[tid];
    __syncthreads();
    int eb = blockIdx.x*32;
    for(int idx=tid; idx<1024; idx+=320){
        int el = idx>>5, h = idx&31;
        int e = eb+el;
        float a = sB1[h];
        if(e<E){
            const float* rb = g_geo + (size_t)e*20 + 8;
            #pragma unroll
            for(int r=0;r<10;r++) a += rb[r]*sW1[r*32+h];
        }
        sh_hid[idx] = siluf(a);
    }
    __syncthreads();
    float w2[32];
    #pragma unroll
    for(int h=0;h<32;h++) w2[h]=W2[h*320+tid];
    for(int el=0; el<32; el++){
        int e = eb+el;
        if(e>=E) break;
        float a=0.f;
        #pragma unroll
        for(int h=0;h<32;h++) a += sh_hid[el*32+h]*w2[h];
        g_wgt[(size_t)e*320+tid] = __float2half(a);
    }
}

// ---------------- fused layer: gather messages (CSR) + node update ----------
__global__ void __launch_bounds__(256, 4) k_fused(
        const float* __restrict__ Ws, const float* __restrict__ Wss,
        const float* __restrict__ Wv, const float* __restrict__ Wvv,
        const float* __restrict__ Wt, const float* __restrict__ Wtt,
        int l, int flip, int N){
    const float* hr_s = flip? g_hsB : g_hsA;
    const float* hr_v = flip? g_hvB : g_hvA;
    const float* hr_t = flip? g_htB : g_htA;
    float* hw_s = flip? g_hsA : g_hsB;
    float* hw_v = flip? g_hvA : g_hvB;
    float* hw_t = flip? g_htA : g_htB;

    __shared__ float sh_a[8*896];
    int lane = threadIdx.x & 31;
    int wloc = threadIdx.x >> 5;
    float* sa = sh_a + wloc*896;   // a0: [0,112) ; a1: 112 + c*3+d ; a2: 496 + c*5+d
    int n = blockIdx.x*8 + wloc;
    if(n>=N) return;

    float acc0[4] = {0.f,0.f,0.f,0.f};
    float acc1[4][3] = {};
    float acc2[3][5] = {};

    int beg = g_off[n], end = g_off[n+1];
    for(int ii=beg; ii<end; ii++){
        int src = g_src[ii];
        const float* Ge = g_geo + (size_t)ii*20;
        float4 Ya = *(const float4*)(Ge);
        float4 Yb = *(const float4*)(Ge+4);
        float y1x=Ya.x, y1y=Ya.y, y1z=Ya.z;
        float y20=Ya.w, y21=Yb.x, y22=Yb.y, y23=Yb.z, y24=Yb.w;
        const __half* W = g_wgt + (size_t)ii*320;
        const float* hs = hr_s + (size_t)src*64;
        float s0 = hs[lane], s1 = hs[lane+32];
        const float* hv = hr_v + (size_t)src*96 + lane*3;
        float v0 = hv[0], v1 = hv[1], v2 = hv[2];
        float t0=0.f,t1=0.f,t2=0.f,t3=0.f,t4=0.f;
        if(lane<16){
            const float* ht = hr_t + (size_t)src*80 + lane*5;
            t0=ht[0]; t1=ht[1]; t2=ht[2]; t3=ht[3]; t4=ht[4];
        }
        acc0[0] += __half2float(W[lane])*s0;
        acc0[1] += __half2float(W[32+lane])*s1;
        acc0[2] += __half2float(W[64+lane])*(v0*y1x + v1*y1y + v2*y1z);
        acc0[3] += __half2float(W[96+(lane&15)])*(t0*y20 + t1*y21 + t2*y22 + t3*y23 + t4*y24);
        float w;
        w = __half2float(W[112+lane])*s0; acc1[0][0]+=w*y1x; acc1[0][1]+=w*y1y; acc1[0][2]+=w*y1z;
        w = __half2float(W[144+lane])*s1; acc1[1][0]+=w*y1x; acc1[1][1]+=w*y1y; acc1[1][2]+=w*y1z;
        w = __half2float(W[176+lane]);    acc1[2][0]+=w*v0;  acc1[2][1]+=w*v1;  acc1[2][2]+=w*v2;
        w = __half2float(W[208+lane]);
        acc1[3][0]+=w*(v1*y1z - v2*y1y);
        acc1[3][1]+=w*(v2*y1x - v0*y1z);
        acc1[3][2]+=w*(v0*y1y - v1*y1x);
        w = __half2float(W[240+lane])*s0; acc2[0][0]+=w*y20; acc2[0][1]+=w*y21; acc2[0][2]+=w*y22; acc2[0][3]+=w*y23; acc2[0][4]+=w*y24;
        w = __half2float(W[272+lane])*s1; acc2[1][0]+=w*y20; acc2[1][1]+=w*y21; acc2[1][2]+=w*y22; acc2[1][3]+=w*y23; acc2[1][4]+=w*y24;
        w = __half2float(W[304+(lane&15)]); acc2[2][0]+=w*t0; acc2[2][1]+=w*t1; acc2[2][2]+=w*t2; acc2[2][3]+=w*t3; acc2[2][4]+=w*t4;
    }

    // stage accumulated messages in shared for the warp
    sa[lane]      = acc0[0];
    sa[32+lane]   = acc0[1];
    sa[64+lane]   = acc0[2];
    if(lane<16) sa[96+lane] = acc0[3];
    #pragma unroll
    for(int k=0;k<4;k++){
        #pragma unroll
        for(int d=0;d<3;d++) sa[112 + (lane+32*k)*3 + d] = acc1[k][d];
    }
    #pragma unroll
    for(int k=0;k<2;k++){
        #pragma unroll
        for(int d=0;d<5;d++) sa[496 + (lane+32*k)*5 + d] = acc2[k][d];
    }
    if(lane<16){
        #pragma unroll
        for(int d=0;d<5;d++) sa[496 + (lane+64)*5 + d] = acc2[2][d];
    }
    __syncwarp();

    // node update: h_s = silu(a0@Ws + h_s@Wss)
    const float* Wsl  = Ws  + l*7168;
    const float* Wssl = Wss + l*4096;
    float o0=0.f, o1=0.f;
    for(int c=0;c<112;c++){
        float a = sa[c];
        o0 += a*Wsl[c*64+lane];
        o1 += a*Wsl[c*64+lane+32];
    }
    const float* hsn = hr_s + (size_t)n*64;
    for(int c=0;c<64;c++){
        float h = hsn[c];
        o0 += h*Wssl[c*64+lane];
        o1 += h*Wssl[c*64+lane+32];
    }
    hw_s[(size_t)n*64+lane]    = siluf(o0);
    hw_s[(size_t)n*64+lane+32] = siluf(o1);

    // h_v = a1@Wv + h_v@Wvv  (per dim d)
    const float* Wvl  = Wv  + l*4096;
    const float* Wvvl = Wvv + l*1024;
    float ov0=0.f, ov1=0.f, ov2=0.f;
    for(int c=0;c<128;c++){
        float wv = Wvl[c*32+lane];
        const float* av = sa + 112 + c*3;
        ov0 += av[0]*wv; ov1 += av[1]*wv; ov2 += av[2]*wv;
    }
    const float* hvn = hr_v + (size_t)n*96;
    for(int c=0;c<32;c++){
        float wv = Wvvl[c*32+lane];
        ov0 += hvn[c*3+0]*wv; ov1 += hvn[c*3+1]*wv; ov2 += hvn[c*3+2]*wv;
    }
    hw_v[(size_t)n*96+lane*3+0]=ov0;
    hw_v[(size_t)n*96+lane*3+1]=ov1;
    hw_v[(size_t)n*96+lane*3+2]=ov2;

    // h_t = a2@Wt + h_t@Wtt
    if(lane<16){
        const float* Wtl  = Wt  + l*1280;
        const float* Wttl = Wtt + l*256;
        float ot0=0.f,ot1=0.f,ot2=0.f,ot3=0.f,ot4=0.f;
        for(int c=0;c<80;c++){
            float wt = Wtl[c*16+lane];
            const float* at = sa + 496 + c*5;
            ot0+=at[0]*wt; ot1+=at[1]*wt; ot2+=at[2]*wt; ot3+=at[3]*wt; ot4+=at[4]*wt;
        }
        const float* htn = hr_t + (size_t)n*80;
        for(int c=0;c<16;c++){
            float wt = Wttl[c*16+lane];
            ot0+=htn[c*5+0]*wt; ot1+=htn[c*5+1]*wt; ot2+=htn[c*5+2]*wt;
            ot3+=htn[c*5+3]*wt; ot4+=htn[c*5+4]*wt;
        }
        hw_t[(size_t)n*80+lane*5+0]=ot0;
        hw_t[(size_t)n*80+lane*5+1]=ot1;
        hw_t[(size_t)n*80+lane*5+2]=ot2;
        hw_t[(size_t)n*80+lane*5+3]=ot3;
        hw_t[(size_t)n*80+lane*5+4]=ot4;
    }
}

// ---------------- attention head projections (shared-staged weights) -------
__global__ void __launch_bounds__(256) k_kv(const float* __restrict__ Wk, const float* __restrict__ Wvp, int N){
    __shared__ float sWk[4096], sWv[4096];
    int tid = threadIdx.x;
    for(int i=tid;i<4096;i+=256){ sWk[i]=Wk[i]; sWv[i]=Wvp[i]; }
    __syncthreads();
    int lane = tid&31, w = tid>>5;
    for(int n = blockIdx.x*8 + w; n < N; n += 8*KV_BLOCKS){
        const float* hs = g_hsA + (size_t)n*64;
        float k0=0.f,k1=0.f,v0=0.f,v1=0.f;
        for(int c=0;c<64;c++){
            float h = hs[c];
            k0 += h*sWk[c*64+lane];
            k1 += h*sWk[c*64+lane+32];
            v0 += h*sWv[c*64+lane];
            v1 += h*sWv[c*64+lane+32];
        }
        g_k[(size_t)n*64+lane]=k0; g_k[(size_t)n*64+lane+32]=k1;
        g_v[(size_t)n*64+lane]=v0; g_v[(size_t)n*64+lane+32]=v1;
    }
}
__global__ void k_q(const float* __restrict__ Wq, const int* __restrict__ absorber, int G){
    int idx = blockIdx.x*blockDim.x+threadIdx.x;
    if(idx>=G*64) return;
    int g = idx>>6, j = idx&63;
    int a = absorber[g];
    const float* hs = g_hsA + (size_t)a*64;
    float acc=0.f;
    #pragma unroll
    for(int c=0;c<64;c++) acc += hs[c]*Wq[c*64+j];
    g_q[idx]=acc;
}

// ---------------- per-graph softmax attention + zr ----------------
__global__ void __launch_bounds__(128) k_attn(const int* __restrict__ absorber){
    int g = blockIdx.x;
    int tid = threadIdx.x, warp = tid>>5, lane = tid&31;
    __shared__ float qsh[64];
    __shared__ float wred[4];
    __shared__ float wc[4][64];
    int s = g_gstart[g], e = g_gstart[g+1];
    if(tid<64) qsh[tid] = g_q[g*64+tid];
    __syncthreads();
    float lmax = -1e30f;
    for(int i=s+warp; i<e; i+=4){
        float p = qsh[lane]*g_k[(size_t)i*64+lane] + qsh[lane+32]*g_k[(size_t)i*64+lane+32];
        #pragma unroll
        for(int o=16;o;o>>=1) p += __shfl_xor_sync(0xffffffffu,p,o);
        lmax = fmaxf(lmax, p*0.125f);
    }
    if(lane==0) wred[warp]=lmax;
    __syncthreads();
    float m = fmaxf(fmaxf(wred[0],wred[1]), fmaxf(wred[2],wred[3]));
    __syncthreads();
    float den=0.f, c0=0.f, c1=0.f;
    for(int i=s+warp; i<e; i+=4){
        float p = qsh[lane]*g_k[(size_t)i*64+lane] + qsh[lane+32]*g_k[(size_t)i*64+lane+32];
        #pragma unroll
        for(int o=16;o;o>>=1) p += __shfl_xor_sync(0xffffffffu,p,o);
        float ex = expf(p*0.125f - m);
        den += ex;
        c0 += ex*g_v[(size_t)i*64+lane];
        c1 += ex*g_v[(size_t)i*64+lane+32];
    }
    wc[warp][lane]=c0; wc[warp][lane+32]=c1;
    if(lane==0) wred[warp]=den;
    __syncthreads();
    int a = absorber[g];
    if(tid<64){
        float cs = wc[0][tid]+wc[1][tid]+wc[2][tid]+wc[3][tid];
        float dt = wred[0]+wred[1]+wred[2]+wred[3];
        g_zr[g*176+tid]    = g_hsA[(size_t)a*64+tid];
        g_zr[g*176+64+tid] = cs/fmaxf(dt,1e-9f);
    }
    if(tid>=64 && tid<96){
        int c = tid-64;
        const float* hv = g_hvA + (size_t)a*96 + c*3;
        g_zr[g*176+128+c] = hv[0]*hv[0]+hv[1]*hv[1]+hv[2]*hv[2];
    }
    if(tid>=96 && tid<112){
        int c = tid-96;
        const float* ht = g_htA + (size_t)a*80 + c*5;
        float sacc=0.f;
        #pragma unroll
        for(int d=0;d<5;d++) sacc += ht[d]*ht[d];
        g_zr[g*176+160+c]=sacc;
    }
}

// ---------------- readout MLP ----------------
__global__ void __launch_bounds__(128) k_out(const float* __restrict__ Wr1, const float* __restrict__ br1,
                                             const float* __restrict__ Wr2, const float* __restrict__ br2,
                                             float* __restrict__ out){
    int g = blockIdx.x, tid = threadIdx.x;
    __shared__ float zsh[176];
    __shared__ float hsh[128];
    for(int i=tid;i<176;i+=128) zsh[i]=g_zr[g*176+i];
    __syncthreads();
    float acc = br1[tid];
    for(int i=0;i<176;i++) acc += zsh[i]*Wr1[i*128+tid];
    hsh[tid]=siluf(acc);
    __syncthreads();
    float o = br2[tid];
    #pragma unroll
    for(int i=0;i<128;i++) o += hsh[i]*Wr2[i*128+tid];
    out[g*128+tid]=o;
}

// ---------------- launch ----------------
extern "C" void kernel_launch(void* const* d_in, const int* in_sizes, int n_in,
                              void* d_out, int out_size){
    const int*   z        = (const int*)  d_in[0];
    const float* pos      = (const float*)d_in[1];
    const int*   ei       = (const int*)  d_in[2];
    const int*   batch    = (const int*)  d_in[3];
    const int*   absorber = (const int*)  d_in[4];
    const float* embed    = (const float*)d_in[5];
    const float* rW1      = (const float*)d_in[6];
    const float* rb1      = (const float*)d_in[7];
    const float* rW2      = (const float*)d_in[8];
    const float* Ws       = (const float*)d_in[9];
    const float* Wss      = (const float*)d_in[10];
    const float* Wv       = (const float*)d_in[11];
    const float* Wvv      = (const float*)d_in[12];
    const float* Wt       = (const float*)d_in[13];
    const float* Wtt      = (const float*)d_in[14];
    const float* Wq       = (const float*)d_in[15];
    const float* Wk       = (const float*)d_in[16];
    const float* Wvp      = (const float*)d_in[17];
    const float* Wr1      = (const float*)d_in[18];
    const float* br1      = (const float*)d_in[19];
    const float* Wr2      = (const float*)d_in[20];
    const float* br2      = (const float*)d_in[21];
    float* out = (float*)d_out;

    int N = in_sizes[0];
    int E = in_sizes[2]/2;
    int G = in_sizes[4];
    if(N>NN || E>NE || G>NG) return;

    int gs_work = N*96 > E ? N*96 : E;

    k_csr   <<<1, 1024>>>(ei, E, N);                               // launch 1
    k_gs    <<<(gs_work+255)/256, 256>>>(pos, ei, z, embed, N, E); // launch 2
    k_gstart<<<(G+1+127)/128, 128>>>(batch, N, G);                 // launch 3

    for(int l=0;l<4;l++){
        k_wgt  <<<(E+31)/32, 320>>>(rW1, rb1, rW2, l, E);          // launch 4 (l=0) <- profiled
        k_fused<<<(N+7)/8, 256>>>(Ws, Wss, Wv, Wvv, Wt, Wtt, l, l&1, N);
    }

    k_kv    <<<KV_BLOCKS, 256>>>(Wk, Wvp, N);
    k_q     <<<(G*64+255)/256, 256>>>(Wq, absorber, G);
    k_attn  <<<G, 128>>>(absorber);
    k_out   <<<G, 128>>>(Wr1, br1, Wr2, br2, out);
}

// round 14
// speedup vs baseline: 1.1974x; 1.0926x over previous
#include <cuda_runtime.h>
#include <cuda_fp16.h>
#include <math.h>

#define NN 20000
#define NE 100000
#define NG 400
#define KV_BLOCKS 296

// ---------------- scratch (static device allocations only) ----------------
__device__ float g_hsA[NN*64], g_hsB[NN*64];
__device__ float g_hvA[NN*96], g_hvB[NN*96];
__device__ float g_htA[NN*80], g_htB[NN*80];
__device__ float g_geo[(size_t)NE*20];     // per CSR-slot: y1[3], y2[5], rb[10], pad2
__device__ __half g_wgt[(size_t)NE*320];   // fp16 edge weights
__device__ int   g_src[NE];
__device__ int   g_off[NN+1];
__device__ int   g_cur[NN];
__device__ float g_k[NN*64], g_v[NN*64], g_q[NG*64];
__device__ int   g_gstart[NG+1];
__device__ float g_zr[NG*176];

__device__ __forceinline__ float siluf(float x){ return x/(1.f+expf(-x)); }

// ---------------- CSR build: zero + count (global atomics) + scan, 1 block --
__global__ void __launch_bounds__(1024) k_csr(const int* __restrict__ ei, int E, int N){
    __shared__ int warpsum[32];
    __shared__ int s_carry;
    int tid = threadIdx.x, lane = tid&31, wid = tid>>5;
    for(int i=tid;i<N;i+=1024) g_cur[i]=0;
    if(tid==0){ s_carry=0; g_off[0]=0; }
    __syncthreads();
    for(int e=tid;e<E;e+=1024) atomicAdd(&g_cur[ei[E+e]],1);
    __syncthreads();
    for(int base=0; base<N; base+=1024){
        int i = base+tid;
        int v = (i<N)? g_cur[i] : 0;
        int x = v;
        #pragma unroll
        for(int o=1;o<32;o<<=1){ int t=__shfl_up_sync(0xffffffffu,x,o); if(lane>=o) x+=t; }
        if(lane==31) warpsum[wid]=x;
        __syncthreads();
        if(wid==0){
            int w = warpsum[lane];
            #pragma unroll
            for(int o=1;o<32;o<<=1){ int t=__shfl_up_sync(0xffffffffu,w,o); if(lane>=o) w+=t; }
            warpsum[lane]=w;
        }
        __syncthreads();
        int incl = x + (wid? warpsum[wid-1]:0) + s_carry;
        if(i<N){ g_off[i+1]=incl; g_cur[i]=incl-v; }
        __syncthreads();
        if(tid==1023) s_carry = incl;
        __syncthreads();
    }
}

// ---------------- geometry + CSR scatter + feature init --------------------
__global__ void k_gs(const float* __restrict__ pos, const int* __restrict__ ei,
                     const int* __restrict__ z, const float* __restrict__ embed,
                     int N, int E){
    int idx = blockIdx.x*blockDim.x+threadIdx.x;
    if(idx < N*96) g_hvA[idx]=0.f;
    if(idx < N*80) g_htA[idx]=0.f;
    if(idx < N*64){
        int n = idx>>6, c = idx&63;
        g_hsA[idx] = embed[z[n]*64+c];
    }
    if(idx >= E) return;
    int e = idx;
    int s = ei[e], d = ei[E+e];
    float vx = pos[3*d+0]-pos[3*s+0];
    float vy = pos[3*d+1]-pos[3*s+1];
    float vz = pos[3*d+2]-pos[3*s+2];
    float elen = sqrtf(vx*vx+vy*vy+vz*vz);
    float inv = 1.f/(elen+1e-9f);
    float x=vx*inv, y=vy*inv, zz=vz*inv;
    const float s3  = 1.7320508075688772f;
    const float h5  = 1.1180339887498949f;
    const float s15 = 3.872983346207417f;
    int p = atomicAdd(&g_cur[d],1);
    g_src[p]=s;
    float* gg = g_geo + (size_t)p*20;
    float4 a0 = make_float4(s3*x, s3*y, s3*zz, s15*x*y);
    float4 a1 = make_float4(s15*y*zz, h5*(3.f*zz*zz-1.f), s15*x*zz, 0.5f*s15*(x*x-y*y));
    *(float4*)(gg)   = a0;
    *(float4*)(gg+4) = a1;
    const float sigma = 5.f/9.f;
    #pragma unroll
    for(int r=0;r<10;r++){
        float t = (elen - (float)r*(5.f/9.f))/sigma;
        gg[8+r] = expf(-0.5f*t*t);
    }
}

// ---------------- group start offsets (binary search on sorted batch) ------
__global__ void k_gstart(const int* __restrict__ batch, int N, int G){
    int g = blockIdx.x*blockDim.x+threadIdx.x;
    if(g>G) return;
    int lo=0, hi=N;
    while(lo<hi){
        int mid=(lo+hi)>>1;
        if(batch[mid]<g) lo=mid+1; else hi=mid;
    }
    g_gstart[g]=lo;
}

// ---------------- per-edge weight MLP: wgt = silu(rb@rW1+rb1)@rW2 ----------
// 160 threads; thread owns adjacent cols (2t,2t+1); packed half2 store.
__global__ void __launch_bounds__(160) k_wgt(const float* __restrict__ rW1,
                                             const float* __restrict__ rb1,
                                             const float* __restrict__ rW2,
                                             int l, int E){
    __shared__ float sh_hid[1024];   // 32 edges x 32 hidden
    __shared__ float sW1[320];
    __shared__ float sB1[32];
    const float* W1 = rW1 + l*320;
    const float* B1 = rb1 + l*32;
    const float* W2 = rW2 + l*10240;
    int tid = threadIdx.x;
    for(int i=tid;i<320;i+=160) sW1[i]=W1[i];
    if(tid<32) sB1[tid]=B1[tid];
    __syncthreads();
    int eb = blockIdx.x*32;
    for(int idx=tid; idx<1024; idx+=160){
        int el = idx>>5, h = idx&31;
        int e = eb+el;
        float a = sB1[h];
        if(e<E){
            const float* rb = g_geo + (size_t)e*20 + 8;
            #pragma unroll
            for(int r=0;r<10;r++) a += rb[r]*sW1[r*32+h];
        }
        sh_hid[idx] = siluf(a);
    }
    __syncthreads();
    float w2a[32], w2b[32];
    #pragma unroll
    for(int h=0;h<32;h++){ w2a[h]=W2[h*320+2*tid]; w2b[h]=W2[h*320+2*tid+1]; }
    for(int el=0; el<32; el++){
        int e = eb+el;
        if(e>=E) break;
        float a=0.f, b=0.f;
        #pragma unroll
        for(int h=0;h<32;h++){
            float hv = sh_hid[el*32+h];
            a += hv*w2a[h];
            b += hv*w2b[h];
        }
        *reinterpret_cast<__half2*>(&g_wgt[(size_t)e*320 + 2*tid]) = __floats2half2_rn(a,b);
    }
}

// ---------------- fused layer: gather (CSR) + node update -------------------
// 2 nodes per warp: gather each node's messages into its own sa buffer, then
// one weight stream updates both nodes (halves GEMV weight wavefronts/node).
__global__ void __launch_bounds__(128, 6) k_fused(
        const float* __restrict__ Ws, const float* __restrict__ Wss,
        const float* __restrict__ Wv, const float* __restrict__ Wvv,
        const float* __restrict__ Wt, const float* __restrict__ Wtt,
        int l, int flip, int N){
    const float* hr_s = flip? g_hsB : g_hsA;
    const float* hr_v = flip? g_hvB : g_hvA;
    const float* hr_t = flip? g_htB : g_htA;
    float* hw_s = flip? g_hsA : g_hsB;
    float* hw_v = flip? g_hvA : g_hvB;
    float* hw_t = flip? g_htA : g_htB;

    __shared__ float sh_a[4*2*896];
    int lane = threadIdx.x & 31;
    int wloc = threadIdx.x >> 5;
    int nbase = blockIdx.x*8 + wloc*2;
    if(nbase>=N) return;
    float* sa0 = sh_a + wloc*2*896;
    float* sa1 = sa0 + 896;

    // ---- gather phase: both nodes sequentially ----
    #pragma unroll 1
    for(int half=0; half<2; half++){
        int n = nbase+half;
        float* sa = half? sa1 : sa0;
        if(n>=N) break;
        float acc0[4] = {0.f,0.f,0.f,0.f};
        float acc1[4][3] = {};
        float acc2[3][5] = {};
        int beg = g_off[n], end = g_off[n+1];
        for(int ii=beg; ii<end; ii++){
            int src = g_src[ii];
            const float* Ge = g_geo + (size_t)ii*20;
            float4 Ya = *(const float4*)(Ge);
            float4 Yb = *(const float4*)(Ge+4);
            float y1x=Ya.x, y1y=Ya.y, y1z=Ya.z;
            float y20=Ya.w, y21=Yb.x, y22=Yb.y, y23=Yb.z, y24=Yb.w;
            const __half* W = g_wgt + (size_t)ii*320;
            const float* hs = hr_s + (size_t)src*64;
            float s0 = hs[lane], s1 = hs[lane+32];
            const float* hv = hr_v + (size_t)src*96 + lane*3;
            float v0 = hv[0], v1 = hv[1], v2 = hv[2];
            float t0=0.f,t1=0.f,t2=0.f,t3=0.f,t4=0.f;
            if(lane<16){
                const float* ht = hr_t + (size_t)src*80 + lane*5;
                t0=ht[0]; t1=ht[1]; t2=ht[2]; t3=ht[3]; t4=ht[4];
            }
            acc0[0] += __half2float(W[lane])*s0;
            acc0[1] += __half2float(W[32+lane])*s1;
            acc0[2] += __half2float(W[64+lane])*(v0*y1x + v1*y1y + v2*y1z);
            acc0[3] += __half2float(W[96+(lane&15)])*(t0*y20 + t1*y21 + t2*y22 + t3*y23 + t4*y24);
            float w;
            w = __half2float(W[112+lane])*s0; acc1[0][0]+=w*y1x; acc1[0][1]+=w*y1y; acc1[0][2]+=w*y1z;
            w = __half2float(W[144+lane])*s1; acc1[1][0]+=w*y1x; acc1[1][1]+=w*y1y; acc1[1][2]+=w*y1z;
            w = __half2float(W[176+lane]);    acc1[2][0]+=w*v0;  acc1[2][1]+=w*v1;  acc1[2][2]+=w*v2;
            w = __half2float(W[208+lane]);
            acc1[3][0]+=w*(v1*y1z - v2*y1y);
            acc1[3][1]+=w*(v2*y1x - v0*y1z);
            acc1[3][2]+=w*(v0*y1y - v1*y1x);
            w = __half2float(W[240+lane])*s0; acc2[0][0]+=w*y20; acc2[0][1]+=w*y21; acc2[0][2]+=w*y22; acc2[0][3]+=w*y23; acc2[0][4]+=w*y24;
            w = __half2float(W[272+lane])*s1; acc2[1][0]+=w*y20; acc2[1][1]+=w*y21; acc2[1][2]+=w*y22; acc2[1][3]+=w*y23; acc2[1][4]+=w*y24;
            w = __half2float(W[304+(lane&15)]); acc2[2][0]+=w*t0; acc2[2][1]+=w*t1; acc2[2][2]+=w*t2; acc2[2][3]+=w*t3; acc2[2][4]+=w*t4;
        }
        sa[lane]      = acc0[0];
        sa[32+lane]   = acc0[1];
        sa[64+lane]   = acc0[2];
        if(lane<16) sa[96+lane] = acc0[3];
        #pragma unroll
        for(int k=0;k<4;k++){
            #pragma unroll
            for(int d=0;d<3;d++) sa[112 + (lane+32*k)*3 + d] = acc1[k][d];
        }
        #pragma unroll
        for(int k=0;k<2;k++){
            #pragma unroll
            for(int d=0;d<5;d++) sa[496 + (lane+32*k)*5 + d] = acc2[k][d];
        }
        if(lane<16){
            #pragma unroll
            for(int d=0;d<5;d++) sa[496 + (lane+64)*5 + d] = acc2[2][d];
        }
    }
    __syncwarp();

    bool has1 = (nbase+1 < N);
    int n0 = nbase;
    int n1 = has1? nbase+1 : nbase;   // redirect reads to avoid OOB; stores predicated

    // ---- h_s = silu(a0@Ws + h_s@Wss), both nodes per weight load ----
    const float* Wsl  = Ws  + l*7168;
    const float* Wssl = Wss + l*4096;
    float o0=0.f,o1=0.f,p0=0.f,p1=0.f;
    for(int c=0;c<112;c++){
        float w0 = Wsl[c*64+lane], w1 = Wsl[c*64+lane+32];
        float a = sa0[c], b = sa1[c];
        o0+=a*w0; o1+=a*w1; p0+=b*w0; p1+=b*w1;
    }
    const float* hs0 = hr_s + (size_t)n0*64;
    const float* hs1 = hr_s + (size_t)n1*64;
    for(int c=0;c<64;c++){
        float w0 = Wssl[c*64+lane], w1 = Wssl[c*64+lane+32];
        float a = hs0[c], b = hs1[c];
        o0+=a*w0; o1+=a*w1; p0+=b*w0; p1+=b*w1;
    }
    hw_s[(size_t)n0*64+lane]    = siluf(o0);
    hw_s[(size_t)n0*64+lane+32] = siluf(o1);
    if(has1){
        hw_s[(size_t)n1*64+lane]    = siluf(p0);
        hw_s[(size_t)n1*64+lane+32] = siluf(p1);
    }

    // ---- h_v = a1@Wv + h_v@Wvv ----
    const float* Wvl  = Wv  + l*4096;
    const float* Wvvl = Wvv + l*1024;
    float ov0=0.f,ov1=0.f,ov2=0.f, pv0=0.f,pv1=0.f,pv2=0.f;
    for(int c=0;c<128;c++){
        float wv = Wvl[c*32+lane];
        const float* a = sa0 + 112 + c*3;
        const float* b = sa1 + 112 + c*3;
        ov0+=a[0]*wv; ov1+=a[1]*wv; ov2+=a[2]*wv;
        pv0+=b[0]*wv; pv1+=b[1]*wv; pv2+=b[2]*wv;
    }
    const float* hv0 = hr_v + (size_t)n0*96;
    const float* hv1 = hr_v + (size_t)n1*96;
    for(int c=0;c<32;c++){
        float wv = Wvvl[c*32+lane];
        ov0+=hv0[c*3+0]*wv; ov1+=hv0[c*3+1]*wv; ov2+=hv0[c*3+2]*wv;
        pv0+=hv1[c*3+0]*wv; pv1+=hv1[c*3+1]*wv; pv2+=hv1[c*3+2]*wv;
    }
    hw_v[(size_t)n0*96+lane*3+0]=ov0;
    hw_v[(size_t)n0*96+lane*3+1]=ov1;
    hw_v[(size_t)n0*96+lane*3+2]=ov2;
    if(has1){
        hw_v[(size_t)n1*96+lane*3+0]=pv0;
        hw_v[(size_t)n1*96+lane*3+1]=pv1;
        hw_v[(size_t)n1*96+lane*3+2]=pv2;
    }

    // ---- h_t = a2@Wt + h_t@Wtt ----
    if(lane<16){
        const float* Wtl  = Wt  + l*1280;
        const float* Wttl = Wtt + l*256;
        float ot[5]={0,0,0,0,0}, pt[5]={0,0,0,0,0};
        for(int c=0;c<80;c++){
            float wt = Wtl[c*16+lane];
            const float* a = sa0 + 496 + c*5;
            const float* b = sa1 + 496 + c*5;
            #pragma unroll
            for(int d=0;d<5;d++){ ot[d]+=a[d]*wt; pt[d]+=b[d]*wt; }
        }
        const float* ht0 = hr_t + (size_t)n0*80;
        const float* ht1 = hr_t + (size_t)n1*80;
        for(int c=0;c<16;c++){
            float wt = Wttl[c*16+lane];
            #pragma unroll
            for(int d=0;d<5;d++){ ot[d]+=ht0[c*5+d]*wt; pt[d]+=ht1[c*5+d]*wt; }
        }
        #pragma unroll
        for(int d=0;d<5;d++) hw_t[(size_t)n0*80+lane*5+d]=ot[d];
        if(has1){
            #pragma unroll
            for(int d=0;d<5;d++) hw_t[(size_t)n1*80+lane*5+d]=pt[d];
        }
    }
}

// ---------------- attention head projections (shared-staged weights) -------
__global__ void __launch_bounds__(256) k_kv(const float* __restrict__ Wk, const float* __restrict__ Wvp, int N){
    __shared__ float sWk[4096], sWv[4096];
    int tid = threadIdx.x;
    for(int i=tid;i<4096;i+=256){ sWk[i]=Wk[i]; sWv[i]=Wvp[i]; }
    __syncthreads();
    int lane = tid&31, w = tid>>5;
    for(int n = blockIdx.x*8 + w; n < N; n += 8*KV_BLOCKS){
        const float* hs = g_hsA + (size_t)n*64;
        float k0=0.f,k1=0.f,v0=0.f,v1=0.f;
        for(int c=0;c<64;c++){
            float h = hs[c];
            k0 += h*sWk[c*64+lane];
            k1 += h*sWk[c*64+lane+32];
            v0 += h*sWv[c*64+lane];
            v1 += h*sWv[c*64+lane+32];
        }
        g_k[(size_t)n*64+lane]=k0; g_k[(size_t)n*64+lane+32]=k1;
        g_v[(size_t)n*64+lane]=v0; g_v[(size_t)n*64+lane+32]=v1;
    }
}
__global__ void k_q(const float* __restrict__ Wq, const int* __restrict__ absorber, int G){
    int idx = blockIdx.x*blockDim.x+threadIdx.x;
    if(idx>=G*64) return;
    int g = idx>>6, j = idx&63;
    int a = absorber[g];
    const float* hs = g_hsA + (size_t)a*64;
    float acc=0.f;
    #pragma unroll
    for(int c=0;c<64;c++) acc += hs[c]*Wq[c*64+j];
    g_q[idx]=acc;
}

// ---------------- per-graph softmax attention + zr ----------------
__global__ void __launch_bounds__(128) k_attn(const int* __restrict__ absorber){
    int g = blockIdx.x;
    int tid = threadIdx.x, warp = tid>>5, lane = tid&31;
    __shared__ float qsh[64];
    __shared__ float wred[4];
    __shared__ float wc[4][64];
    int s = g_gstart[g], e = g_gstart[g+1];
    if(tid<64) qsh[tid] = g_q[g*64+tid];
    __syncthreads();
    float lmax = -1e30f;
    for(int i=s+warp; i<e; i+=4){
        float p = qsh[lane]*g_k[(size_t)i*64+lane] + qsh[lane+32]*g_k[(size_t)i*64+lane+32];
        #pragma unroll
        for(int o=16;o;o>>=1) p += __shfl_xor_sync(0xffffffffu,p,o);
        lmax = fmaxf(lmax, p*0.125f);
    }
    if(lane==0) wred[warp]=lmax;
    __syncthreads();
    float m = fmaxf(fmaxf(wred[0],wred[1]), fmaxf(wred[2],wred[3]));
    __syncthreads();
    float den=0.f, c0=0.f, c1=0.f;
    for(int i=s+warp; i<e; i+=4){
        float p = qsh[lane]*g_k[(size_t)i*64+lane] + qsh[lane+32]*g_k[(size_t)i*64+lane+32];
        #pragma unroll
        for(int o=16;o;o>>=1) p += __shfl_xor_sync(0xffffffffu,p,o);
        float ex = expf(p*0.125f - m);
        den += ex;
        c0 += ex*g_v[(size_t)i*64+lane];
        c1 += ex*g_v[(size_t)i*64+lane+32];
    }
    wc[warp][lane]=c0; wc[warp][lane+32]=c1;
    if(lane==0) wred[warp]=den;
    __syncthreads();
    int a = absorber[g];
    if(tid<64){
        float cs = wc[0][tid]+wc[1][tid]+wc[2][tid]+wc[3][tid];
        float dt = wred[0]+wred[1]+wred[2]+wred[3];
        g_zr[g*176+tid]    = g_hsA[(size_t)a*64+tid];
        g_zr[g*176+64+tid] = cs/fmaxf(dt,1e-9f);
    }
    if(tid>=64 && tid<96){
        int c = tid-64;
        const float* hv = g_hvA + (size_t)a*96 + c*3;
        g_zr[g*176+128+c] = hv[0]*hv[0]+hv[1]*hv[1]+hv[2]*hv[2];
    }
    if(tid>=96 && tid<112){
        int c = tid-96;
        const float* ht = g_htA + (size_t)a*80 + c*5;
        float sacc=0.f;
        #pragma unroll
        for(int d=0;d<5;d++) sacc += ht[d]*ht[d];
        g_zr[g*176+160+c]=sacc;
    }
}

// ---------------- readout MLP ----------------
__global__ void __launch_bounds__(128) k_out(const float* __restrict__ Wr1, const float* __restrict__ br1,
                                             const float* __restrict__ Wr2, const float* __restrict__ br2,
                                             float* __restrict__ out){
    int g = blockIdx.x, tid = threadIdx.x;
    __shared__ float zsh[176];
    __shared__ float hsh[128];
    for(int i=tid;i<176;i+=128) zsh[i]=g_zr[g*176+i];
    __syncthreads();
    float acc = br1[tid];
    for(int i=0;i<176;i++) acc += zsh[i]*Wr1[i*128+tid];
    hsh[tid]=siluf(acc);
    __syncthreads();
    float o = br2[tid];
    #pragma unroll
    for(int i=0;i<128;i++) o += hsh[i]*Wr2[i*128+tid];
    out[g*128+tid]=o;
}

// ---------------- launch ----------------
extern "C" void kernel_launch(void* const* d_in, const int* in_sizes, int n_in,
                              void* d_out, int out_size){
    const int*   z        = (const int*)  d_in[0];
    const float* pos      = (const float*)d_in[1];
    const int*   ei       = (const int*)  d_in[2];
    const int*   batch    = (const int*)  d_in[3];
    const int*   absorber = (const int*)  d_in[4];
    const float* embed    = (const float*)d_in[5];
    const float* rW1      = (const float*)d_in[6];
    const float* rb1      = (const float*)d_in[7];
    const float* rW2      = (const float*)d_in[8];
    const float* Ws       = (const float*)d_in[9];
    const float* Wss      = (const float*)d_in[10];
    const float* Wv       = (const float*)d_in[11];
    const float* Wvv      = (const float*)d_in[12];
    const float* Wt       = (const float*)d_in[13];
    const float* Wtt      = (const float*)d_in[14];
    const float* Wq       = (const float*)d_in[15];
    const float* Wk       = (const float*)d_in[16];
    const float* Wvp      = (const float*)d_in[17];
    const float* Wr1      = (const float*)d_in[18];
    const float* br1      = (const float*)d_in[19];
    const float* Wr2      = (const float*)d_in[20];
    const float* br2      = (const float*)d_in[21];
    float* out = (float*)d_out;

    int N = in_sizes[0];
    int E = in_sizes[2]/2;
    int G = in_sizes[4];
    if(N>NN || E>NE || G>NG) return;

    int gs_work = N*96 > E ? N*96 : E;

    k_csr <<<1, 1024>>>(ei, E, N);                                 // launch 1
    k_gs  <<<(gs_work+255)/256, 256>>>(pos, ei, z, embed, N, E);   // launch 2

    for(int l=0;l<4;l++){
        k_wgt  <<<(E+31)/32, 160>>>(rW1, rb1, rW2, l, E);          // launch 3 (l=0)
        k_fused<<<(N+7)/8, 128>>>(Ws, Wss, Wv, Wvv, Wt, Wtt, l, l&1, N); // launch 4 (l=0) <- profiled
    }

    k_gstart<<<(G+1+127)/128, 128>>>(batch, N, G);
    k_kv    <<<KV_BLOCKS, 256>>>(Wk, Wvp, N);
    k_q     <<<(G*64+255)/256, 256>>>(Wq, absorber, G);
    k_attn  <<<G, 128>>>(absorber);
    k_out   <<<G, 128>>>(Wr1, br1, Wr2, br2, out);
}